// round 2
// baseline (speedup 1.0000x reference)
#include <cuda_runtime.h>

#define B_ 64
#define C_ 64
#define T_ 4000
#define TCH 25           // T-chunks for gram kernel (4000/25 = 160 t per CTA)
#define TILE_T 32
#define TILES_PER 5      // 160 / 32
#define COLP 68          // col buffer pitch (floats)
#define ROWP 132         // dup row buffer pitch (floats, 16B-aligned rows)
#define TC_C 160         // t-chunk width for apply kernel
#define NCH_C 25
#define ADP 132          // apply: dup attention pitch

// Scratch (static device globals — allocation-free)
__device__ float g_gp[B_ * TCH * C_ * C_];   // partial Grams
__device__ float g_sxp[B_ * TCH * C_];       // partial channel sums
__device__ float g_at[B_ * C_ * C_];         // attention matrix M[r][s]

typedef unsigned long long u64t;

__device__ __forceinline__ void ffma2(u64t& d, u64t a, u64t b) {
    asm("fma.rn.f32x2 %0, %1, %2, %0;" : "+l"(d) : "l"(a), "l"(b));
}
__device__ __forceinline__ float2 funp(u64t v) {
    float2 r; asm("mov.b64 {%0, %1}, %2;" : "=f"(r.x), "=f"(r.y) : "l"(v)); return r;
}

// ---------------------------------------------------------------------------
// Kernel A: partial Gram G[c][e] over this CTA's 160-t range + partial sums.
// Grid (TCH, B_), 128 threads. Thread (ty 0..15, tx 0..7) owns 4 rows x 8 cols.
// Rows live in smem pre-duplicated as (v,v) 8B pairs -> FFMA2 operands come
// straight from 2 broadcast LDS.128; cols as 2 LDS.128 of packed pairs.
// Double-buffered smem + register prefetch, one barrier per tile.
// ---------------------------------------------------------------------------
__global__ void __launch_bounds__(128) k_gram(const float* __restrict__ x) {
    extern __shared__ float dsm[];
    float* sc0 = dsm;                       // [2][TILE_T][COLP]
    float* sr0 = dsm + 2 * TILE_T * COLP;   // [2][TILE_T][ROWP]
    __shared__ float red[256];

    const int b  = blockIdx.y;
    const int tc = blockIdx.x;
    const int tid = threadIdx.x;
    const int ty = tid >> 3, tx = tid & 7;
    const int ca = tid >> 2;     // channel 0..31 (also loads ca+32)
    const int tq = tid & 3;      // t-quad slot
    const float* xb = x + (size_t)b * C_ * T_;
    const int t0 = tc * (TILES_PER * TILE_T);

    u64t acc[4][4];
#pragma unroll
    for (int i = 0; i < 4; ++i)
#pragma unroll
        for (int j = 0; j < 4; ++j) acc[i][j] = 0ull;

    float sxa = 0.f, sxb = 0.f;
    const float* pA = xb + (size_t)ca * T_ + t0;
    const float* pB = xb + (size_t)(ca + 32) * T_ + t0;

    // prefetch tile 0: 2 quads per channel (t = 4tq and 16+4tq)
    float4 a0 = *(const float4*)(pA + 4 * tq);
    float4 a1 = *(const float4*)(pA + 16 + 4 * tq);
    float4 b0 = *(const float4*)(pB + 4 * tq);
    float4 b1 = *(const float4*)(pB + 16 + 4 * tq);

#pragma unroll 1
    for (int tile = 0; tile < TILES_PER; ++tile) {
        float* sc = sc0 + (tile & 1) * (TILE_T * COLP);
        float* sr = sr0 + (tile & 1) * (TILE_T * ROWP);

        sxa += a0.x + a0.y + a0.z + a0.w + a1.x + a1.y + a1.z + a1.w;
        sxb += b0.x + b0.y + b0.z + b0.w + b1.x + b1.y + b1.z + b1.w;

        // stage cols (scalar) + dup rows (8B pairs)
        const float av[8] = {a0.x, a0.y, a0.z, a0.w, a1.x, a1.y, a1.z, a1.w};
        const float bv[8] = {b0.x, b0.y, b0.z, b0.w, b1.x, b1.y, b1.z, b1.w};
#pragma unroll
        for (int j = 0; j < 4; ++j) {
            const int tA = 4 * tq + j, tB = 16 + 4 * tq + j;
            sc[tA * COLP + ca] = av[j];
            sc[tB * COLP + ca] = av[4 + j];
            sc[tA * COLP + ca + 32] = bv[j];
            sc[tB * COLP + ca + 32] = bv[4 + j];
            *(float2*)&sr[tA * ROWP + 2 * ca]        = make_float2(av[j], av[j]);
            *(float2*)&sr[tB * ROWP + 2 * ca]        = make_float2(av[4 + j], av[4 + j]);
            *(float2*)&sr[tA * ROWP + 2 * (ca + 32)] = make_float2(bv[j], bv[j]);
            *(float2*)&sr[tB * ROWP + 2 * (ca + 32)] = make_float2(bv[4 + j], bv[4 + j]);
        }

        // prefetch next tile (LDG issued before the barrier)
        if (tile + 1 < TILES_PER) {
            const int off = (tile + 1) * TILE_T;
            a0 = *(const float4*)(pA + off + 4 * tq);
            a1 = *(const float4*)(pA + off + 16 + 4 * tq);
            b0 = *(const float4*)(pB + off + 4 * tq);
            b1 = *(const float4*)(pB + off + 16 + 4 * tq);
        }
        __syncthreads();

#pragma unroll
        for (int t = 0; t < TILE_T; ++t) {
            ulonglong2 ra  = *(const ulonglong2*)&sr[t * ROWP + 8 * ty];      // (r0,r0)(r1,r1)
            ulonglong2 rb  = *(const ulonglong2*)&sr[t * ROWP + 8 * ty + 4];  // (r2,r2)(r3,r3)
            ulonglong2 cv0 = *(const ulonglong2*)&sc[t * COLP + 8 * tx];      // (c0c1)(c2c3)
            ulonglong2 cv1 = *(const ulonglong2*)&sc[t * COLP + 8 * tx + 4];  // (c4c5)(c6c7)
            ffma2(acc[0][0], ra.x, cv0.x); ffma2(acc[0][1], ra.x, cv0.y);
            ffma2(acc[0][2], ra.x, cv1.x); ffma2(acc[0][3], ra.x, cv1.y);
            ffma2(acc[1][0], ra.y, cv0.x); ffma2(acc[1][1], ra.y, cv0.y);
            ffma2(acc[1][2], ra.y, cv1.x); ffma2(acc[1][3], ra.y, cv1.y);
            ffma2(acc[2][0], rb.x, cv0.x); ffma2(acc[2][1], rb.x, cv0.y);
            ffma2(acc[2][2], rb.x, cv1.x); ffma2(acc[2][3], rb.x, cv1.y);
            ffma2(acc[3][0], rb.y, cv0.x); ffma2(acc[3][1], rb.y, cv0.y);
            ffma2(acc[3][2], rb.y, cv1.x); ffma2(acc[3][3], rb.y, cv1.y);
        }
    }

    // write 4x8 partial tile
    float* gp = g_gp + (size_t)(b * TCH + tc) * (C_ * C_);
#pragma unroll
    for (int i = 0; i < 4; ++i) {
        const int row = 4 * ty + i;
        float2 p0 = funp(acc[i][0]), p1 = funp(acc[i][1]);
        float2 p2 = funp(acc[i][2]), p3 = funp(acc[i][3]);
        *(float4*)(gp + row * C_ + 8 * tx)     = make_float4(p0.x, p0.y, p1.x, p1.y);
        *(float4*)(gp + row * C_ + 8 * tx + 4) = make_float4(p2.x, p2.y, p3.x, p3.y);
    }

    // per-channel partial sums
    red[tid] = sxa;
    red[128 + tid] = sxb;
    __syncthreads();
    if (tid < 64) {
        const int base = (tid < 32) ? (4 * tid) : (128 + 4 * (tid - 32));
        float s = red[base] + red[base + 1] + red[base + 2] + red[base + 3];
        g_sxp[(b * TCH + tc) * C_ + tid] = s;
    }
}

// ---------------------------------------------------------------------------
// Kernel B: reduce partials, E~[c][e] = S11*G + S21*sx[e], min-max + softmax.
// ---------------------------------------------------------------------------
__global__ void __launch_bounds__(256) k_attn(const float* __restrict__ w1,
                                              const float* __restrict__ b1,
                                              const float* __restrict__ w2,
                                              const float* __restrict__ b2) {
    __shared__ float Es[C_][65];
    __shared__ float sxs[C_];
    const int b = blockIdx.x;
    const int tid = threadIdx.x;

    float S11 = 0.f, S21 = 0.f;
#pragma unroll
    for (int j = 0; j < 8; ++j) { S11 += w1[j] * w2[j]; S21 += b1[j] * w2[j]; }

    if (tid < 64) {
        float s = 0.f;
#pragma unroll
        for (int p = 0; p < TCH; ++p) s += g_sxp[(b * TCH + p) * C_ + tid];
        sxs[tid] = s;
    }
    __syncthreads();

    const float* gp = g_gp + (size_t)b * TCH * (C_ * C_);
    for (int i = tid; i < C_ * C_; i += 256) {
        float g = 0.f;
#pragma unroll
        for (int p = 0; p < TCH; ++p) g += gp[p * (C_ * C_) + i];
        const int e = i & 63;
        Es[i >> 6][e] = S11 * g + S21 * sxs[e];
    }
    __syncthreads();

    const int wid = tid >> 5, lane = tid & 31;
    float* at = g_at + (size_t)b * (C_ * C_);
    for (int r = wid; r < C_; r += 8) {
        float v0 = Es[r][lane], v1 = Es[r][lane + 32];
        float mx = fmaxf(v0, v1), mn = fminf(v0, v1);
#pragma unroll
        for (int o = 16; o; o >>= 1) {
            mx = fmaxf(mx, __shfl_xor_sync(0xffffffffu, mx, o));
            mn = fminf(mn, __shfl_xor_sync(0xffffffffu, mn, o));
        }
        const float inv = 1.f / (mx - mn + 1e-8f);
        const float nmax = (mx - mn) * inv;
        float e0 = expf((v0 - mn) * inv - nmax);
        float e1 = expf((v1 - mn) * inv - nmax);
        float s = e0 + e1;
#pragma unroll
        for (int o = 16; o; o >>= 1) s += __shfl_xor_sync(0xffffffffu, s, o);
        const float invs = 1.f / s;
        at[r * C_ + lane]      = e0 * invs;
        at[r * C_ + lane + 32] = e1 * invs;
    }
}

// ---------------------------------------------------------------------------
// Kernel C: out[c,t] = x[c,t] + gamma * sum_r M[r][c] * x[r][t].
// Attention row values staged pre-duplicated -> FFMA2 operands direct from
// broadcast LDS.128 (no MOV dup).
// ---------------------------------------------------------------------------
__global__ void __launch_bounds__(256) k_apply(const float* __restrict__ x,
                                               const float* __restrict__ gptr,
                                               float* __restrict__ out) {
    extern __shared__ float dsm[];
    float* Ad  = dsm;                 // [64][ADP] duplicated attention (v,v)
    float* xsc = dsm + C_ * ADP;      // [64][160] x chunk
    const int b  = blockIdx.y;
    const int ck = blockIdx.x;
    const int t0 = ck * TC_C;
    const int tid = threadIdx.x;

    const float* at = g_at + (size_t)b * (C_ * C_);
    for (int i = tid; i < C_ * C_; i += 256) {
        const float v = at[i];
        *(float2*)&Ad[(i >> 6) * ADP + 2 * (i & 63)] = make_float2(v, v);
    }

    const float* xb = x + (size_t)b * C_ * T_;
#pragma unroll
    for (int k = 0; k < 10; ++k) {
        const int v = tid + k * 256;   // 0..2559 float4 slots
        const int e = v / 40, q = v % 40;
        *(float4*)&xsc[e * TC_C + 4 * q] =
            *(const float4*)(xb + (size_t)e * T_ + t0 + 4 * q);
    }
    __syncthreads();

    const int ty = tid >> 4, tx = tid & 15;
    u64t acc[4][5];
#pragma unroll
    for (int i = 0; i < 4; ++i)
#pragma unroll
        for (int p = 0; p < 5; ++p) acc[i][p] = 0ull;

#pragma unroll 4
    for (int r = 0; r < C_; ++r) {
        ulonglong2 a01 = *(const ulonglong2*)&Ad[r * ADP + 8 * ty];      // (a0,a0)(a1,a1)
        ulonglong2 a23 = *(const ulonglong2*)&Ad[r * ADP + 8 * ty + 4];  // (a2,a2)(a3,a3)
        const float* xrow = &xsc[r * TC_C + 2 * tx];
#pragma unroll
        for (int p = 0; p < 5; ++p) {
            u64t xv = *(const u64t*)(xrow + 32 * p);
            ffma2(acc[0][p], a01.x, xv);
            ffma2(acc[1][p], a01.y, xv);
            ffma2(acc[2][p], a23.x, xv);
            ffma2(acc[3][p], a23.y, xv);
        }
    }

    const float gmv = *gptr;
    float* ob = out + (size_t)b * C_ * T_;
#pragma unroll
    for (int i = 0; i < 4; ++i) {
        const int c = 4 * ty + i;
#pragma unroll
        for (int p = 0; p < 5; ++p) {
            const int t = 2 * tx + 32 * p;
            float2 a = funp(acc[i][p]);
            const float xv0 = xsc[c * TC_C + t];
            const float xv1 = xsc[c * TC_C + t + 1];
            float2 o = make_float2(fmaf(gmv, a.x, xv0), fmaf(gmv, a.y, xv1));
            *(float2*)(ob + (size_t)c * T_ + t0 + t) = o;
        }
    }
}

// ---------------------------------------------------------------------------
extern "C" void kernel_launch(void* const* d_in, const int* in_sizes, int n_in,
                              void* d_out, int out_size) {
    const float* x  = (const float*)d_in[0];
    const float* w1 = (const float*)d_in[1];
    const float* b1 = (const float*)d_in[2];
    const float* w2 = (const float*)d_in[3];
    const float* b2 = (const float*)d_in[4];
    const float* gm = (const float*)d_in[5];
    float* out = (float*)d_out;

    const int smem_gram  = 2 * TILE_T * (COLP + ROWP) * (int)sizeof(float);  // 51,200 B
    const int smem_apply = (C_ * ADP + C_ * TC_C) * (int)sizeof(float);      // 74,752 B
    cudaFuncSetAttribute(k_gram,  cudaFuncAttributeMaxDynamicSharedMemorySize, smem_gram);
    cudaFuncSetAttribute(k_apply, cudaFuncAttributeMaxDynamicSharedMemorySize, smem_apply);

    k_gram<<<dim3(TCH, B_), 128, smem_gram>>>(x);
    k_attn<<<B_, 256>>>(w1, b1, w2, b2);
    k_apply<<<dim3(NCH_C, B_), 256, smem_apply>>>(x, gm, out);
}

// round 3
// speedup vs baseline: 1.0803x; 1.0803x over previous
#include <cuda_runtime.h>

#define B_ 64
#define C_ 64
#define T_ 4000
#define TCH 25           // T-chunks for gram kernel (4000/25 = 160 t per CTA)
#define TILE_T 32
#define TILES_PER 5      // 160 / 32
#define COLP 68          // col buffer pitch (floats)
#define ROWP 132         // dup row buffer pitch (floats)
#define TC_C 160         // t-chunk width for apply kernel
#define NCH_C 25
#define ADP 132          // apply: dup attention pitch

// Scratch (static device globals — allocation-free)
__device__ float g_gp[B_ * TCH * C_ * C_];   // partial Grams
__device__ float g_sxp[B_ * TCH * C_];       // partial channel sums
__device__ float g_at[B_ * C_ * C_];         // attention matrix M[r][s]

typedef unsigned long long u64t;

__device__ __forceinline__ void ffma2(u64t& d, u64t a, u64t b) {
    asm("fma.rn.f32x2 %0, %1, %2, %0;" : "+l"(d) : "l"(a), "l"(b));
}
__device__ __forceinline__ float2 funp(u64t v) {
    float2 r; asm("mov.b64 {%0, %1}, %2;" : "=f"(r.x), "=f"(r.y) : "l"(v)); return r;
}

// ---------------------------------------------------------------------------
// Kernel A: partial Gram G[c][e] over this CTA's 160-t range + partial sums.
// Grid (TCH, B_), 256 threads (R1 shape: occ ~66%). Thread (ty,tx) in 16x16
// owns a 4x4 tile. Rows staged PRE-DUPLICATED as (v,v) pairs so FFMA2
// operands come straight from broadcast LDS.128 — no MOV duplication.
// Inner loop: 3 LDS.128 + 8 FFMA2 per t (was 2 LDS + 8 MOV + 8 FFMA2).
// ---------------------------------------------------------------------------
__global__ void __launch_bounds__(256) k_gram(const float* __restrict__ x) {
    extern __shared__ float dsm[];
    float* sc = dsm;                    // [TILE_T][COLP]  scalar cols
    float* sr = dsm + TILE_T * COLP;    // [TILE_T][ROWP]  dup rows
    __shared__ float red[512];

    const int b  = blockIdx.y;
    const int tc = blockIdx.x;
    const int tid = threadIdx.x;
    const int ty = tid >> 4, tx = tid & 15;
    const int ca = tid >> 3;   // channel 0..31 (also loads ca+32)
    const int tq = tid & 7;    // float4 slot within 32-t tile
    const float* xb = x + (size_t)b * C_ * T_;
    const int t0 = tc * (TILES_PER * TILE_T);

    u64t acc[4][2];
#pragma unroll
    for (int i = 0; i < 4; ++i) { acc[i][0] = 0ull; acc[i][1] = 0ull; }

    float sxa = 0.f, sxb = 0.f;
    const float* pA = xb + (size_t)ca * T_ + t0;
    const float* pB = xb + (size_t)(ca + 32) * T_ + t0;

#pragma unroll 1
    for (int tile = 0; tile < TILES_PER; ++tile) {
        const int tb = tile * TILE_T;
        float4 va = *(const float4*)(pA + tb + 4 * tq);
        float4 vb = *(const float4*)(pB + tb + 4 * tq);
        sxa += va.x + va.y + va.z + va.w;
        sxb += vb.x + vb.y + vb.z + vb.w;

        __syncthreads();   // previous tile's compute done before overwrite
        const float av[4] = {va.x, va.y, va.z, va.w};
        const float bv[4] = {vb.x, vb.y, vb.z, vb.w};
#pragma unroll
        for (int j = 0; j < 4; ++j) {
            const int t = 4 * tq + j;
            sc[t * COLP + ca]        = av[j];
            sc[t * COLP + ca + 32]   = bv[j];
            *(float2*)&sr[t * ROWP + 2 * ca]        = make_float2(av[j], av[j]);
            *(float2*)&sr[t * ROWP + 2 * (ca + 32)] = make_float2(bv[j], bv[j]);
        }
        __syncthreads();

#pragma unroll 8
        for (int t = 0; t < TILE_T; ++t) {
            ulonglong2 ra = *(const ulonglong2*)&sr[t * ROWP + 8 * ty];      // (r0,r0)(r1,r1)
            ulonglong2 rb = *(const ulonglong2*)&sr[t * ROWP + 8 * ty + 4];  // (r2,r2)(r3,r3)
            ulonglong2 cv = *(const ulonglong2*)&sc[t * COLP + 4 * tx];      // (c0,c1)(c2,c3)
            ffma2(acc[0][0], ra.x, cv.x); ffma2(acc[0][1], ra.x, cv.y);
            ffma2(acc[1][0], ra.y, cv.x); ffma2(acc[1][1], ra.y, cv.y);
            ffma2(acc[2][0], rb.x, cv.x); ffma2(acc[2][1], rb.x, cv.y);
            ffma2(acc[3][0], rb.y, cv.x); ffma2(acc[3][1], rb.y, cv.y);
        }
    }

    // write 4x4 partial tile (coalesced float4 per row)
    float* gp = g_gp + (size_t)(b * TCH + tc) * (C_ * C_);
#pragma unroll
    for (int i = 0; i < 4; ++i) {
        float2 p0 = funp(acc[i][0]);
        float2 p1 = funp(acc[i][1]);
        *(float4*)(gp + (4 * ty + i) * C_ + 4 * tx) = make_float4(p0.x, p0.y, p1.x, p1.y);
    }

    // per-channel partial sums
    red[tid] = sxa;
    red[256 + tid] = sxb;
    __syncthreads();
    if (tid < 64) {
        const int base = (tid < 32) ? (8 * tid) : (256 + 8 * (tid - 32));
        float s = 0.f;
#pragma unroll
        for (int u = 0; u < 8; ++u) s += red[base + u];
        g_sxp[(b * TCH + tc) * C_ + tid] = s;
    }
}

// ---------------------------------------------------------------------------
// Kernel B: reduce partials, E~[c][e] = S11*G + S21*sx[e], min-max + softmax.
// ---------------------------------------------------------------------------
__global__ void __launch_bounds__(256) k_attn(const float* __restrict__ w1,
                                              const float* __restrict__ b1,
                                              const float* __restrict__ w2,
                                              const float* __restrict__ b2) {
    __shared__ float Es[C_][65];
    __shared__ float sxs[C_];
    const int b = blockIdx.x;
    const int tid = threadIdx.x;

    float S11 = 0.f, S21 = 0.f;
#pragma unroll
    for (int j = 0; j < 8; ++j) { S11 += w1[j] * w2[j]; S21 += b1[j] * w2[j]; }

    if (tid < 64) {
        float s = 0.f;
#pragma unroll
        for (int p = 0; p < TCH; ++p) s += g_sxp[(b * TCH + p) * C_ + tid];
        sxs[tid] = s;
    }
    __syncthreads();

    const float* gp = g_gp + (size_t)b * TCH * (C_ * C_);
    for (int i = tid; i < C_ * C_; i += 256) {
        float g = 0.f;
#pragma unroll
        for (int p = 0; p < TCH; ++p) g += gp[p * (C_ * C_) + i];
        const int e = i & 63;
        Es[i >> 6][e] = S11 * g + S21 * sxs[e];
    }
    __syncthreads();

    const int wid = tid >> 5, lane = tid & 31;
    float* at = g_at + (size_t)b * (C_ * C_);
    for (int r = wid; r < C_; r += 8) {
        float v0 = Es[r][lane], v1 = Es[r][lane + 32];
        float mx = fmaxf(v0, v1), mn = fminf(v0, v1);
#pragma unroll
        for (int o = 16; o; o >>= 1) {
            mx = fmaxf(mx, __shfl_xor_sync(0xffffffffu, mx, o));
            mn = fminf(mn, __shfl_xor_sync(0xffffffffu, mn, o));
        }
        const float inv = 1.f / (mx - mn + 1e-8f);
        const float nmax = (mx - mn) * inv;
        float e0 = expf((v0 - mn) * inv - nmax);
        float e1 = expf((v1 - mn) * inv - nmax);
        float s = e0 + e1;
#pragma unroll
        for (int o = 16; o; o >>= 1) s += __shfl_xor_sync(0xffffffffu, s, o);
        const float invs = 1.f / s;
        at[r * C_ + lane]      = e0 * invs;
        at[r * C_ + lane + 32] = e1 * invs;
    }
}

// ---------------------------------------------------------------------------
// Kernel C: out[c,t] = x[c,t] + gamma * sum_r M[r][c] * x[r][t].
// Attention rows staged pre-duplicated -> FFMA2 operands direct from
// broadcast LDS.128 (no MOV dup).
// ---------------------------------------------------------------------------
__global__ void __launch_bounds__(256) k_apply(const float* __restrict__ x,
                                               const float* __restrict__ gptr,
                                               float* __restrict__ out) {
    extern __shared__ float dsm[];
    float* Ad  = dsm;                 // [64][ADP] duplicated attention (v,v)
    float* xsc = dsm + C_ * ADP;      // [64][160] x chunk
    const int b  = blockIdx.y;
    const int ck = blockIdx.x;
    const int t0 = ck * TC_C;
    const int tid = threadIdx.x;

    const float* at = g_at + (size_t)b * (C_ * C_);
    for (int i = tid; i < C_ * C_; i += 256) {
        const float v = at[i];
        *(float2*)&Ad[(i >> 6) * ADP + 2 * (i & 63)] = make_float2(v, v);
    }

    const float* xb = x + (size_t)b * C_ * T_;
#pragma unroll
    for (int k = 0; k < 10; ++k) {
        const int v = tid + k * 256;   // 0..2559 float4 slots
        const int e = v / 40, q = v % 40;
        *(float4*)&xsc[e * TC_C + 4 * q] =
            *(const float4*)(xb + (size_t)e * T_ + t0 + 4 * q);
    }
    __syncthreads();

    const int ty = tid >> 4, tx = tid & 15;
    u64t acc[4][5];
#pragma unroll
    for (int i = 0; i < 4; ++i)
#pragma unroll
        for (int p = 0; p < 5; ++p) acc[i][p] = 0ull;

#pragma unroll 4
    for (int r = 0; r < C_; ++r) {
        ulonglong2 a01 = *(const ulonglong2*)&Ad[r * ADP + 8 * ty];      // (a0,a0)(a1,a1)
        ulonglong2 a23 = *(const ulonglong2*)&Ad[r * ADP + 8 * ty + 4];  // (a2,a2)(a3,a3)
        const float* xrow = &xsc[r * TC_C + 2 * tx];
#pragma unroll
        for (int p = 0; p < 5; ++p) {
            u64t xv = *(const u64t*)(xrow + 32 * p);
            ffma2(acc[0][p], a01.x, xv);
            ffma2(acc[1][p], a01.y, xv);
            ffma2(acc[2][p], a23.x, xv);
            ffma2(acc[3][p], a23.y, xv);
        }
    }

    const float gmv = *gptr;
    float* ob = out + (size_t)b * C_ * T_;
#pragma unroll
    for (int i = 0; i < 4; ++i) {
        const int c = 4 * ty + i;
#pragma unroll
        for (int p = 0; p < 5; ++p) {
            const int t = 2 * tx + 32 * p;
            float2 a = funp(acc[i][p]);
            const float xv0 = xsc[c * TC_C + t];
            const float xv1 = xsc[c * TC_C + t + 1];
            float2 o = make_float2(fmaf(gmv, a.x, xv0), fmaf(gmv, a.y, xv1));
            *(float2*)(ob + (size_t)c * T_ + t0 + t) = o;
        }
    }
}

// ---------------------------------------------------------------------------
extern "C" void kernel_launch(void* const* d_in, const int* in_sizes, int n_in,
                              void* d_out, int out_size) {
    const float* x  = (const float*)d_in[0];
    const float* w1 = (const float*)d_in[1];
    const float* b1 = (const float*)d_in[2];
    const float* w2 = (const float*)d_in[3];
    const float* b2 = (const float*)d_in[4];
    const float* gm = (const float*)d_in[5];
    float* out = (float*)d_out;

    const int smem_gram  = TILE_T * (COLP + ROWP) * (int)sizeof(float);  // 25,600 B
    const int smem_apply = (C_ * ADP + C_ * TC_C) * (int)sizeof(float);  // 74,752 B
    cudaFuncSetAttribute(k_gram,  cudaFuncAttributeMaxDynamicSharedMemorySize, smem_gram);
    cudaFuncSetAttribute(k_apply, cudaFuncAttributeMaxDynamicSharedMemorySize, smem_apply);

    k_gram<<<dim3(TCH, B_), 256, smem_gram>>>(x);
    k_attn<<<B_, 256>>>(w1, b1, w2, b2);
    k_apply<<<dim3(NCH_C, B_), 256, smem_apply>>>(x, gm, out);
}

// round 6
// speedup vs baseline: 1.8501x; 1.7127x over previous
#include <cuda_runtime.h>
#include <cuda_bf16.h>
#include <cstdint>

#define B_ 64
#define C_ 64
#define T_ 4000
#define TS_ 5            // t-splits for gram
#define TSPAN 800        // t per split
#define NSTG 13          // stages of 64 t (12 full + half stage zero-padded)
#define TC_C 160         // t-chunk width for apply kernel
#define NCH_C 25

// Scratch (static device globals — allocation-free)
__device__ float g_gp[B_ * TS_ * C_ * C_];   // partial Grams (5.2 MB)
__device__ float g_sxp[B_ * TS_ * C_];       // partial channel sums
__device__ float g_at[B_ * C_ * C_];         // attention matrix M[r][s]

// single dynamic-smem symbol shared by all kernels
extern __shared__ float smem_dyn[];

__device__ __forceinline__ uint32_t smem_u32(const void* p) {
    uint32_t a;
    asm("{ .reg .u64 t; cvta.to.shared.u64 t, %1; cvt.u32.u64 %0, t; }" : "=r"(a) : "l"(p));
    return a;
}

#define LDSM4(r, addr)                                                       \
    asm volatile("ldmatrix.sync.aligned.m8n8.x4.shared.b16 {%0,%1,%2,%3}, [%4];" \
        : "=r"((r)[0]), "=r"((r)[1]), "=r"((r)[2]), "=r"((r)[3]) : "r"(addr))

#define LDSM4T(r, addr)                                                      \
    asm volatile("ldmatrix.sync.aligned.m8n8.x4.trans.shared.b16 {%0,%1,%2,%3}, [%4];" \
        : "=r"((r)[0]), "=r"((r)[1]), "=r"((r)[2]), "=r"((r)[3]) : "r"(addr))

#define MMA16816(c, a, b0v, b1v)                                             \
    asm volatile("mma.sync.aligned.m16n8k16.row.col.f32.bf16.bf16.f32 "      \
        "{%0,%1,%2,%3}, {%4,%5,%6,%7}, {%8,%9}, {%0,%1,%2,%3};"              \
        : "+f"((c)[0]), "+f"((c)[1]), "+f"((c)[2]), "+f"((c)[3])             \
        : "r"((a)[0]), "r"((a)[1]), "r"((a)[2]), "r"((a)[3]),                \
          "r"(b0v), "r"(b1v))

__device__ __forceinline__ void cvt_hilo(float4 v, uint2& hp, uint2& lp) {
    __nv_bfloat16 h0 = __float2bfloat16(v.x), h1 = __float2bfloat16(v.y);
    __nv_bfloat16 h2 = __float2bfloat16(v.z), h3 = __float2bfloat16(v.w);
    __nv_bfloat16 l0 = __float2bfloat16(v.x - __bfloat162float(h0));
    __nv_bfloat16 l1 = __float2bfloat16(v.y - __bfloat162float(h1));
    __nv_bfloat16 l2 = __float2bfloat16(v.z - __bfloat162float(h2));
    __nv_bfloat16 l3 = __float2bfloat16(v.w - __bfloat162float(h3));
    hp.x = (uint32_t)__bfloat16_as_ushort(h0) | ((uint32_t)__bfloat16_as_ushort(h1) << 16);
    hp.y = (uint32_t)__bfloat16_as_ushort(h2) | ((uint32_t)__bfloat16_as_ushort(h3) << 16);
    lp.x = (uint32_t)__bfloat16_as_ushort(l0) | ((uint32_t)__bfloat16_as_ushort(l1) << 16);
    lp.y = (uint32_t)__bfloat16_as_ushort(l2) | ((uint32_t)__bfloat16_as_ushort(l3) << 16);
}

// ---------------------------------------------------------------------------
// Kernel A (HMMA): partial Gram for one batch over an 800-t split.
// Grid (TS_, B_), 256 threads = 8 warps tiling 64x64 as 4m x 2n.
// G = Xh*Xh^T + P + P^T, P = Xh*Xl^T. Stages of 64 t in swizzled smem.
// ---------------------------------------------------------------------------
__global__ void __launch_bounds__(256) k_gram_mma(const float* __restrict__ x) {
    uint16_t* sh_hi = (uint16_t*)smem_dyn;   // [64][64] bf16, swizzled (8KB)
    uint16_t* sh_lo = sh_hi + 4096;          // (8KB); lo = hi + 8192 bytes
    __shared__ float red[256];

    const int split = blockIdx.x;
    const int b = blockIdx.y;
    const int tid = threadIdx.x;
    const int lane = tid & 31, wid = tid >> 5;
    const int mg = wid >> 1, ng = wid & 1;

    const uint32_t base_hi = smem_u32(sh_hi);

    // staging: thread -> (channel row, 16-t quarter)
    const int srow = tid >> 2, sq = tid & 3;
    const float* xrow = x + ((size_t)b * C_ + srow) * T_ + split * TSPAN;

    // ldmatrix lane addressing
    const int arow = 16 * mg + (lane & 7) + 8 * ((lane >> 3) & 1);
    const int achk = lane >> 4;
    const int brow0 = 32 * ng + 8 * (lane >> 4) + (lane & 7);  // n8 groups 0,1
    const int brow1 = brow0 + 16;                               // n8 groups 2,3
    const int bchk = (lane >> 3) & 1;

    float D1[4][4], D2[4][4];
#pragma unroll
    for (int j = 0; j < 4; ++j)
#pragma unroll
        for (int i = 0; i < 4; ++i) { D1[j][i] = 0.f; D2[j][i] = 0.f; }
    float sx = 0.f;

#pragma unroll 1
    for (int s = 0; s < NSTG; ++s) {
        __syncthreads();
#pragma unroll
        for (int i = 0; i < 4; ++i) {
            const int col = sq * 16 + 4 * i;
            const bool pad = (s == NSTG - 1) && (sq >= 2);
            float4 v = pad ? make_float4(0.f, 0.f, 0.f, 0.f)
                           : *(const float4*)(xrow + s * 64 + col);
            sx += v.x + v.y + v.z + v.w;
            uint2 hp, lp;
            cvt_hilo(v, hp, lp);
            const int ad = srow * 128 + ((((col >> 3) ^ (srow & 7))) << 4) + ((col & 7) << 1);
            *(uint2*)((char*)sh_hi + ad) = hp;
            *(uint2*)((char*)sh_lo + ad) = lp;
        }
        __syncthreads();
#pragma unroll
        for (int k = 0; k < 4; ++k) {
            const int c0 = k * 2;
            uint32_t a[4], bh[8], bl[8];
            const uint32_t aad  = base_hi + arow * 128 + (((c0 + achk) ^ (arow & 7)) << 4);
            const uint32_t b0ad = base_hi + brow0 * 128 + (((c0 + bchk) ^ (brow0 & 7)) << 4);
            const uint32_t b1ad = base_hi + brow1 * 128 + (((c0 + bchk) ^ (brow1 & 7)) << 4);
            LDSM4(a, aad);
            LDSM4(bh + 0, b0ad);       LDSM4(bh + 4, b1ad);
            LDSM4(bl + 0, b0ad + 8192); LDSM4(bl + 4, b1ad + 8192);
#pragma unroll
            for (int j = 0; j < 4; ++j) {
                MMA16816(D1[j], a, bh[2 * j], bh[2 * j + 1]);
                MMA16816(D2[j], a, bl[2 * j], bl[2 * j + 1]);
            }
        }
    }

    // channel sums (4 threads per channel)
    red[tid] = sx;
    __syncthreads();
    if (tid < 64)
        g_sxp[(b * TS_ + split) * C_ + tid] =
            red[4 * tid] + red[4 * tid + 1] + red[4 * tid + 2] + red[4 * tid + 3];
    __syncthreads();

    // epilogue: G = D1 + D2 + D2^T (transpose via smem, pitch 68)
    float* Ds = smem_dyn;
    const int crow = 16 * mg + (lane >> 2);
    const int ccol0 = 32 * ng + 2 * (lane & 3);
#pragma unroll
    for (int j = 0; j < 4; ++j) {
        const int c = ccol0 + 8 * j;
        Ds[crow * 68 + c]           = D2[j][0];
        Ds[crow * 68 + c + 1]       = D2[j][1];
        Ds[(crow + 8) * 68 + c]     = D2[j][2];
        Ds[(crow + 8) * 68 + c + 1] = D2[j][3];
    }
    __syncthreads();
    float* gp = g_gp + (size_t)(b * TS_ + split) * (C_ * C_);
#pragma unroll
    for (int j = 0; j < 4; ++j) {
        const int c = ccol0 + 8 * j;
        float2 o0, o1;
        o0.x = D1[j][0] + D2[j][0] + Ds[c * 68 + crow];
        o0.y = D1[j][1] + D2[j][1] + Ds[(c + 1) * 68 + crow];
        o1.x = D1[j][2] + D2[j][2] + Ds[c * 68 + crow + 8];
        o1.y = D1[j][3] + D2[j][3] + Ds[(c + 1) * 68 + crow + 8];
        *(float2*)(gp + crow * C_ + c) = o0;
        *(float2*)(gp + (crow + 8) * C_ + c) = o1;
    }
}

// ---------------------------------------------------------------------------
// Kernel B: reduce partials, E~[c][e] = S11*G + S21*sx[e], min-max + softmax.
// ---------------------------------------------------------------------------
__global__ void __launch_bounds__(256) k_attn(const float* __restrict__ w1,
                                              const float* __restrict__ b1,
                                              const float* __restrict__ w2,
                                              const float* __restrict__ b2) {
    __shared__ float Es[C_][65];
    __shared__ float sxs[C_];
    const int b = blockIdx.x;
    const int tid = threadIdx.x;

    float S11 = 0.f, S21 = 0.f;
#pragma unroll
    for (int j = 0; j < 8; ++j) { S11 += w1[j] * w2[j]; S21 += b1[j] * w2[j]; }

    if (tid < 64) {
        float s = 0.f;
#pragma unroll
        for (int p = 0; p < TS_; ++p) s += g_sxp[(b * TS_ + p) * C_ + tid];
        sxs[tid] = s;
    }
    __syncthreads();

    const float* gp = g_gp + (size_t)b * TS_ * (C_ * C_);
    for (int i = tid; i < C_ * C_; i += 256) {
        float g = 0.f;
#pragma unroll
        for (int p = 0; p < TS_; ++p) g += gp[p * (C_ * C_) + i];
        const int e = i & 63;
        Es[i >> 6][e] = S11 * g + S21 * sxs[e];
    }
    __syncthreads();

    const int wid = tid >> 5, lane = tid & 31;
    float* at = g_at + (size_t)b * (C_ * C_);
    for (int r = wid; r < C_; r += 8) {
        float v0 = Es[r][lane], v1 = Es[r][lane + 32];
        float mx = fmaxf(v0, v1), mn = fminf(v0, v1);
#pragma unroll
        for (int o = 16; o; o >>= 1) {
            mx = fmaxf(mx, __shfl_xor_sync(0xffffffffu, mx, o));
            mn = fminf(mn, __shfl_xor_sync(0xffffffffu, mn, o));
        }
        const float inv = 1.f / (mx - mn + 1e-8f);
        const float nmax = (mx - mn) * inv;
        float e0 = expf((v0 - mn) * inv - nmax);
        float e1 = expf((v1 - mn) * inv - nmax);
        float s = e0 + e1;
#pragma unroll
        for (int o = 16; o; o >>= 1) s += __shfl_xor_sync(0xffffffffu, s, o);
        const float invs = 1.f / s;
        at[r * C_ + lane]      = e0 * invs;
        at[r * C_ + lane + 32] = e1 * invs;
    }
}

// ---------------------------------------------------------------------------
// Kernel C (HMMA): out[c,t] = x[c,t] + gamma * (M^T X)[c,t].
// Grid (NCH_C, B_), 256 threads = 8 warps (4m x 2n), CTA tile 64 x 160, K=64.
// A = M^T staged hi/lo (ldmatrix), B = X staged hi/lo (ldmatrix.trans).
// acc = Ah*Bh + Al*Bh + Ah*Bl.
// ---------------------------------------------------------------------------
__global__ void __launch_bounds__(256) k_apply_mma(const float* __restrict__ x,
                                                   const float* __restrict__ gptr,
                                                   float* __restrict__ out) {
    uint16_t* At_hi = (uint16_t*)smem_dyn;      // [64][64] pitch 128B (8KB)
    uint16_t* At_lo = At_hi + 4096;             // +8192 bytes
    uint16_t* Xh    = At_lo + 4096;             // [64][192] pitch 384B (24KB)
    uint16_t* Xl    = Xh + 64 * 192;            // +24576 bytes

    const int b = blockIdx.y, ck = blockIdx.x;
    const int t0 = ck * TC_C;
    const int tid = threadIdx.x, lane = tid & 31, wid = tid >> 5;
    const int mg = wid >> 1, ngw = wid & 1;

    // stage Mt (transposed attention) hi/lo, swizzled
    const float* at = g_at + (size_t)b * (C_ * C_);
    for (int i = tid; i < C_ * C_; i += 256) {
        const int r = i >> 6, c = i & 63;
        const float v = at[i];
        __nv_bfloat16 h = __float2bfloat16(v);
        __nv_bfloat16 l = __float2bfloat16(v - __bfloat162float(h));
        const int ad = c * 128 + ((((r >> 3) ^ (c & 7))) << 4) + ((r & 7) << 1);
        *(uint16_t*)((char*)At_hi + ad) = __bfloat16_as_ushort(h);
        *(uint16_t*)((char*)At_lo + ad) = __bfloat16_as_ushort(l);
    }

    // stage X chunk hi/lo, swizzled (pitch 24 chunks of 16B)
    const float* xb = x + (size_t)b * C_ * T_;
#pragma unroll
    for (int k = 0; k < 10; ++k) {
        const int v = tid + k * 256;       // 2560 float4 slots
        const int row = v / 40, q = v % 40;
        float4 w = *(const float4*)(xb + (size_t)row * T_ + t0 + 4 * q);
        uint2 hp, lp;
        cvt_hilo(w, hp, lp);
        const int col = 4 * q;
        const int ad = row * 384 + ((((col >> 3) ^ (row & 7))) << 4) + ((col & 7) << 1);
        *(uint2*)((char*)Xh + ad) = hp;
        *(uint2*)((char*)Xl + ad) = lp;
    }
    __syncthreads();

    float acc[10][4];
#pragma unroll
    for (int j = 0; j < 10; ++j)
#pragma unroll
        for (int i = 0; i < 4; ++i) acc[j][i] = 0.f;

    const uint32_t baseA = smem_u32(At_hi);
    const uint32_t baseX = smem_u32(Xh);
    const int arow = 16 * mg + (lane & 7) + 8 * ((lane >> 3) & 1);
    const int achk = lane >> 4;
    const int bkoff = 8 * ((lane >> 3) & 1) + (lane & 7);
    const int bjj = lane >> 4;

#pragma unroll
    for (int kk = 0; kk < 4; ++kk) {
        uint32_t ah[4], al[4];
        const uint32_t aad = baseA + arow * 128 + (((kk * 2 + achk) ^ (arow & 7)) << 4);
        LDSM4(ah, aad);
        LDSM4(al, aad + 8192);
        const int krow = kk * 16 + bkoff;
#pragma unroll
        for (int p = 0; p < 5; ++p) {
            const int nchunk = ngw * 10 + 2 * p + bjj;
            const uint32_t xad = baseX + krow * 384 + ((nchunk ^ (krow & 7)) << 4);
            uint32_t bh[4], bl[4];
            LDSM4T(bh, xad);
            LDSM4T(bl, xad + 24576);
            MMA16816(acc[2 * p], ah, bh[0], bh[1]);
            MMA16816(acc[2 * p], al, bh[0], bh[1]);
            MMA16816(acc[2 * p], ah, bl[0], bl[1]);
            MMA16816(acc[2 * p + 1], ah, bh[2], bh[3]);
            MMA16816(acc[2 * p + 1], al, bh[2], bh[3]);
            MMA16816(acc[2 * p + 1], ah, bl[2], bl[3]);
        }
    }

    // epilogue: out = x + gamma*acc (x re-read from global, L2-hot)
    const float gmv = *gptr;
    const int orow = 16 * mg + (lane >> 2);
    const int ocol0 = ngw * 80 + 2 * (lane & 3);
    float* ob = out + (size_t)b * C_ * T_ + t0;
    const float* xg = xb + t0;
#pragma unroll
    for (int j = 0; j < 10; ++j) {
        const int tcol = ocol0 + 8 * (j >> 1) * 2 + 8 * (j & 1);
        const int jj = j; // acc[j] covers n8 group j of this warp
        const int tc = ngw * 80 + 8 * jj + 2 * (lane & 3);
        float2 x0 = *(const float2*)(xg + (size_t)orow * T_ + tc);
        float2 x1 = *(const float2*)(xg + (size_t)(orow + 8) * T_ + tc);
        float2 o0 = make_float2(fmaf(gmv, acc[j][0], x0.x), fmaf(gmv, acc[j][1], x0.y));
        float2 o1 = make_float2(fmaf(gmv, acc[j][2], x1.x), fmaf(gmv, acc[j][3], x1.y));
        *(float2*)(ob + (size_t)orow * T_ + tc) = o0;
        *(float2*)(ob + (size_t)(orow + 8) * T_ + tc) = o1;
        (void)tcol;
    }
}

// ---------------------------------------------------------------------------
extern "C" void kernel_launch(void* const* d_in, const int* in_sizes, int n_in,
                              void* d_out, int out_size) {
    const float* x  = (const float*)d_in[0];
    const float* w1 = (const float*)d_in[1];
    const float* b1 = (const float*)d_in[2];
    const float* w2 = (const float*)d_in[3];
    const float* b2 = (const float*)d_in[4];
    const float* gm = (const float*)d_in[5];
    float* out = (float*)d_out;

    const int smem_gram  = 64 * 68 * (int)sizeof(float);     // 17,408 B (>= 16K stage)
    const int smem_apply = 8192 + 8192 + 24576 + 24576;      // 65,536 B
    cudaFuncSetAttribute(k_gram_mma,  cudaFuncAttributeMaxDynamicSharedMemorySize, smem_gram);
    cudaFuncSetAttribute(k_apply_mma, cudaFuncAttributeMaxDynamicSharedMemorySize, smem_apply);

    k_gram_mma<<<dim3(TS_, B_), 256, smem_gram>>>(x);
    k_attn<<<B_, 256>>>(w1, b1, w2, b2);
    k_apply_mma<<<dim3(NCH_C, B_), 256, smem_apply>>>(x, gm, out);
}

// round 7
// speedup vs baseline: 2.2061x; 1.1924x over previous
#include <cuda_runtime.h>
#include <cuda_fp16.h>
#include <cstdint>

#define B_ 64
#define C_ 64
#define T_ 4000
#define TS_ 10           // t-splits for gram
#define TSPAN 400        // t per split
#define NSTG 7           // stages of 64 t (6 full + 16-t remainder)
#define TC_C 160         // t-chunk width for apply kernel
#define NCH_C 25

// Scratch (static device globals — allocation-free)
__device__ float g_gp[B_ * TS_ * C_ * C_];   // partial Grams (10.5 MB)
__device__ float g_sxp[B_ * TS_ * C_];       // partial channel sums
__device__ float g_at[B_ * C_ * C_];         // attention matrix M[r][s]

// single dynamic-smem symbol shared by all kernels
extern __shared__ float smem_dyn[];

__device__ __forceinline__ uint32_t smem_u32(const void* p) {
    uint32_t a;
    asm("{ .reg .u64 t; cvta.to.shared.u64 t, %1; cvt.u32.u64 %0, t; }" : "=r"(a) : "l"(p));
    return a;
}

#define LDSM4(r, addr)                                                       \
    asm volatile("ldmatrix.sync.aligned.m8n8.x4.shared.b16 {%0,%1,%2,%3}, [%4];" \
        : "=r"((r)[0]), "=r"((r)[1]), "=r"((r)[2]), "=r"((r)[3]) : "r"(addr))

#define LDSM4T(r, addr)                                                      \
    asm volatile("ldmatrix.sync.aligned.m8n8.x4.trans.shared.b16 {%0,%1,%2,%3}, [%4];" \
        : "=r"((r)[0]), "=r"((r)[1]), "=r"((r)[2]), "=r"((r)[3]) : "r"(addr))

#define MMAF16(c, a, b0v, b1v)                                               \
    asm volatile("mma.sync.aligned.m16n8k16.row.col.f32.f16.f16.f32 "        \
        "{%0,%1,%2,%3}, {%4,%5,%6,%7}, {%8,%9}, {%0,%1,%2,%3};"              \
        : "+f"((c)[0]), "+f"((c)[1]), "+f"((c)[2]), "+f"((c)[3])             \
        : "r"((a)[0]), "r"((a)[1]), "r"((a)[2]), "r"((a)[3]),                \
          "r"(b0v), "r"(b1v))

__device__ __forceinline__ uint2 cvt_h4(float4 v) {
    __half2 p0 = __floats2half2_rn(v.x, v.y);
    __half2 p1 = __floats2half2_rn(v.z, v.w);
    uint2 r;
    r.x = *(uint32_t*)&p0;
    r.y = *(uint32_t*)&p1;
    return r;
}

// ---------------------------------------------------------------------------
// Kernel A (HMMA fp16): partial Gram for one batch over a 400-t split.
// Grid (TS_, B_), 256 threads = 8 warps tiling 64x64 as 4m x 2n.
// Double-buffered 64-t stages, register prefetch, one sync per stage.
// ---------------------------------------------------------------------------
__global__ void __launch_bounds__(256) k_gram_mma(const float* __restrict__ x) {
    uint16_t* sbuf = (uint16_t*)smem_dyn;   // 2 x [64][64] fp16, swizzled (2 x 8KB)
    __shared__ float red[256];

    const int split = blockIdx.x;
    const int b = blockIdx.y;
    const int tid = threadIdx.x;
    const int lane = tid & 31, wid = tid >> 5;
    const int mg = wid >> 1, ng = wid & 1;

    const uint32_t base = smem_u32(sbuf);

    // staging: thread -> (channel row, 16-t quarter)
    const int srow = tid >> 2, sq = tid & 3;
    const float* xrow = x + ((size_t)b * C_ + srow) * T_ + split * TSPAN;

    // ldmatrix lane addressing
    const int arow = 16 * mg + (lane & 7) + 8 * ((lane >> 3) & 1);
    const int achk = lane >> 4;
    const int brow0 = 32 * ng + 8 * (lane >> 4) + (lane & 7);   // n8 groups 0,1
    const int brow1 = brow0 + 16;                                // n8 groups 2,3
    const int bchk = (lane >> 3) & 1;

    float D[4][4];
#pragma unroll
    for (int j = 0; j < 4; ++j)
#pragma unroll
        for (int i = 0; i < 4; ++i) D[j][i] = 0.f;
    float sx = 0.f;

    // prefetch stage 0 (sq*16 .. sq*16+15)
    float4 v[4];
#pragma unroll
    for (int i = 0; i < 4; ++i) v[i] = *(const float4*)(xrow + sq * 16 + 4 * i);

#pragma unroll 1
    for (int s = 0; s < NSTG; ++s) {
        // convert + store current stage into buffer s&1
        uint16_t* sb = sbuf + (s & 1) * 4096;
#pragma unroll
        for (int i = 0; i < 4; ++i) {
            sx += v[i].x + v[i].y + v[i].z + v[i].w;
            uint2 hp = cvt_h4(v[i]);
            const int col = sq * 16 + 4 * i;
            const int ad = srow * 128 + ((((col >> 3) ^ (srow & 7))) << 4) + ((col & 7) << 1);
            *(uint2*)((char*)sb + ad) = hp;
        }
        // prefetch next stage (guarded: stage 6 keeps only first 16 t)
        if (s + 1 < NSTG) {
            const bool pad = (s + 1 == NSTG - 1) && (sq >= 1);
            const float* src = xrow + (s + 1) * 64 + sq * 16;
#pragma unroll
            for (int i = 0; i < 4; ++i)
                v[i] = pad ? make_float4(0.f, 0.f, 0.f, 0.f)
                           : *(const float4*)(src + 4 * i);
        }
        __syncthreads();

        const uint32_t sbb = base + (s & 1) * 8192;
#pragma unroll
        for (int k = 0; k < 4; ++k) {
            const int c0 = k * 2;
            uint32_t a[4], bh[8];
            LDSM4(a, sbb + arow * 128 + (((c0 + achk) ^ (arow & 7)) << 4));
            LDSM4(bh + 0, sbb + brow0 * 128 + (((c0 + bchk) ^ (brow0 & 7)) << 4));
            LDSM4(bh + 4, sbb + brow1 * 128 + (((c0 + bchk) ^ (brow1 & 7)) << 4));
#pragma unroll
            for (int j = 0; j < 4; ++j)
                MMAF16(D[j], a, bh[2 * j], bh[2 * j + 1]);
        }
    }

    // channel sums (4 threads per channel)
    red[tid] = sx;
    __syncthreads();
    if (tid < 64)
        g_sxp[(b * TS_ + split) * C_ + tid] =
            red[4 * tid] + red[4 * tid + 1] + red[4 * tid + 2] + red[4 * tid + 3];

    // epilogue: write D tile directly
    float* gp = g_gp + (size_t)(b * TS_ + split) * (C_ * C_);
    const int crow = 16 * mg + (lane >> 2);
    const int ccol0 = 32 * ng + 2 * (lane & 3);
#pragma unroll
    for (int j = 0; j < 4; ++j) {
        const int c = ccol0 + 8 * j;
        *(float2*)(gp + crow * C_ + c)       = make_float2(D[j][0], D[j][1]);
        *(float2*)(gp + (crow + 8) * C_ + c) = make_float2(D[j][2], D[j][3]);
    }
}

// ---------------------------------------------------------------------------
// Kernel B: reduce partials, E~[c][e] = S11*G + S21*sx[e], min-max + softmax.
// ---------------------------------------------------------------------------
__global__ void __launch_bounds__(256) k_attn(const float* __restrict__ w1,
                                              const float* __restrict__ b1,
                                              const float* __restrict__ w2,
                                              const float* __restrict__ b2) {
    __shared__ float Es[C_][65];
    __shared__ float sxs[C_];
    const int b = blockIdx.x;
    const int tid = threadIdx.x;

    float S11 = 0.f, S21 = 0.f;
#pragma unroll
    for (int j = 0; j < 8; ++j) { S11 += w1[j] * w2[j]; S21 += b1[j] * w2[j]; }

    if (tid < 64) {
        float s = 0.f;
#pragma unroll
        for (int p = 0; p < TS_; ++p) s += g_sxp[(b * TS_ + p) * C_ + tid];
        sxs[tid] = s;
    }
    __syncthreads();

    const float* gp = g_gp + (size_t)b * TS_ * (C_ * C_);
    for (int i = tid; i < C_ * C_; i += 256) {
        float g = 0.f;
#pragma unroll
        for (int p = 0; p < TS_; ++p) g += gp[p * (C_ * C_) + i];
        const int e = i & 63;
        Es[i >> 6][e] = S11 * g + S21 * sxs[e];
    }
    __syncthreads();

    const int wid = tid >> 5, lane = tid & 31;
    float* at = g_at + (size_t)b * (C_ * C_);
    for (int r = wid; r < C_; r += 8) {
        float v0 = Es[r][lane], v1 = Es[r][lane + 32];
        float mx = fmaxf(v0, v1), mn = fminf(v0, v1);
#pragma unroll
        for (int o = 16; o; o >>= 1) {
            mx = fmaxf(mx, __shfl_xor_sync(0xffffffffu, mx, o));
            mn = fminf(mn, __shfl_xor_sync(0xffffffffu, mn, o));
        }
        const float inv = 1.f / (mx - mn + 1e-8f);
        const float nmax = (mx - mn) * inv;
        float e0 = expf((v0 - mn) * inv - nmax);
        float e1 = expf((v1 - mn) * inv - nmax);
        float s = e0 + e1;
#pragma unroll
        for (int o = 16; o; o >>= 1) s += __shfl_xor_sync(0xffffffffu, s, o);
        const float invs = 1.f / s;
        at[r * C_ + lane]      = e0 * invs;
        at[r * C_ + lane + 32] = e1 * invs;
    }
}

// ---------------------------------------------------------------------------
// Kernel C (HMMA fp16): out[c,t] = x[c,t] + gamma * (M^T X)[c,t].
// Grid (NCH_C, B_), 256 threads = 8 warps (4m x 2n), CTA tile 64 x 160, K=64.
// A = M^T (ldmatrix), B = X (ldmatrix.trans). Single fp16 term.
// ---------------------------------------------------------------------------
__global__ void __launch_bounds__(256) k_apply_mma(const float* __restrict__ x,
                                                   const float* __restrict__ gptr,
                                                   float* __restrict__ out) {
    uint16_t* At = (uint16_t*)smem_dyn;     // [64][64] fp16, pitch 128B (8KB)
    uint16_t* Xs = At + 4096;               // [64][192] fp16, pitch 384B (24KB)

    const int b = blockIdx.y, ck = blockIdx.x;
    const int t0 = ck * TC_C;
    const int tid = threadIdx.x, lane = tid & 31, wid = tid >> 5;
    const int mg = wid >> 1, ngw = wid & 1;

    // stage Mt (transposed attention), swizzled
    const float* at = g_at + (size_t)b * (C_ * C_);
    for (int i = tid; i < C_ * C_; i += 256) {
        const int r = i >> 6, c = i & 63;
        const __half h = __float2half_rn(at[i]);
        const int ad = c * 128 + ((((r >> 3) ^ (c & 7))) << 4) + ((r & 7) << 1);
        *(uint16_t*)((char*)At + ad) = *(const uint16_t*)&h;
    }

    // stage X chunk, swizzled (pitch 24 chunks of 16B)
    const float* xb = x + (size_t)b * C_ * T_;
#pragma unroll
    for (int k = 0; k < 10; ++k) {
        const int v = tid + k * 256;       // 2560 float4 slots
        const int row = v / 40, q = v % 40;
        float4 w = *(const float4*)(xb + (size_t)row * T_ + t0 + 4 * q);
        uint2 hp = cvt_h4(w);
        const int col = 4 * q;
        const int ad = row * 384 + ((((col >> 3) ^ (row & 7))) << 4) + ((col & 7) << 1);
        *(uint2*)((char*)Xs + ad) = hp;
    }
    __syncthreads();

    float acc[10][4];
#pragma unroll
    for (int j = 0; j < 10; ++j)
#pragma unroll
        for (int i = 0; i < 4; ++i) acc[j][i] = 0.f;

    const uint32_t baseA = smem_u32(At);
    const uint32_t baseX = smem_u32(Xs);
    const int arow = 16 * mg + (lane & 7) + 8 * ((lane >> 3) & 1);
    const int achk = lane >> 4;
    const int bkoff = 8 * ((lane >> 3) & 1) + (lane & 7);
    const int bjj = lane >> 4;

#pragma unroll
    for (int kk = 0; kk < 4; ++kk) {
        uint32_t ah[4];
        LDSM4(ah, baseA + arow * 128 + (((kk * 2 + achk) ^ (arow & 7)) << 4));
        const int krow = kk * 16 + bkoff;
#pragma unroll
        for (int p = 0; p < 5; ++p) {
            const int nchunk = ngw * 10 + 2 * p + bjj;
            uint32_t bh[4];
            LDSM4T(bh, baseX + krow * 384 + ((nchunk ^ (krow & 7)) << 4));
            MMAF16(acc[2 * p],     ah, bh[0], bh[1]);
            MMAF16(acc[2 * p + 1], ah, bh[2], bh[3]);
        }
    }

    // epilogue: out = x + gamma*acc (x re-read from global, L2-hot)
    const float gmv = *gptr;
    const int orow = 16 * mg + (lane >> 2);
    float* ob = out + (size_t)b * C_ * T_ + t0;
    const float* xg = xb + t0;
#pragma unroll
    for (int j = 0; j < 10; ++j) {
        const int tc = ngw * 80 + 8 * j + 2 * (lane & 3);
        float2 x0 = *(const float2*)(xg + (size_t)orow * T_ + tc);
        float2 x1 = *(const float2*)(xg + (size_t)(orow + 8) * T_ + tc);
        float2 o0 = make_float2(fmaf(gmv, acc[j][0], x0.x), fmaf(gmv, acc[j][1], x0.y));
        float2 o1 = make_float2(fmaf(gmv, acc[j][2], x1.x), fmaf(gmv, acc[j][3], x1.y));
        *(float2*)(ob + (size_t)orow * T_ + tc) = o0;
        *(float2*)(ob + (size_t)(orow + 8) * T_ + tc) = o1;
    }
}

// ---------------------------------------------------------------------------
extern "C" void kernel_launch(void* const* d_in, const int* in_sizes, int n_in,
                              void* d_out, int out_size) {
    const float* x  = (const float*)d_in[0];
    const float* w1 = (const float*)d_in[1];
    const float* b1 = (const float*)d_in[2];
    const float* w2 = (const float*)d_in[3];
    const float* b2 = (const float*)d_in[4];
    const float* gm = (const float*)d_in[5];
    float* out = (float*)d_out;

    const int smem_gram  = 2 * 8192;           // 16,384 B (double-buffered fp16 stage)
    const int smem_apply = 8192 + 24576;       // 32,768 B
    cudaFuncSetAttribute(k_gram_mma,  cudaFuncAttributeMaxDynamicSharedMemorySize, smem_gram);
    cudaFuncSetAttribute(k_apply_mma, cudaFuncAttributeMaxDynamicSharedMemorySize, smem_apply);

    k_gram_mma<<<dim3(TS_, B_), 256, smem_gram>>>(x);
    k_attn<<<B_, 256>>>(w1, b1, w2, b2);
    k_apply_mma<<<dim3(NCH_C, B_), 256, smem_apply>>>(x, gm, out);
}

// round 8
// speedup vs baseline: 2.3578x; 1.0688x over previous
#include <cuda_runtime.h>
#include <cuda_fp16.h>
#include <cstdint>

#define B_ 64
#define C_ 64
#define T_ 4000
#define TS_ 10           // t-splits for gram
#define TSPAN 400        // t per split
#define NSTG 7           // stages of 64 t (6 full + 16-t remainder)
#define TC_C 160         // t-chunk width for apply kernel
#define NCH_C 25
#define CHPC 2           // chunks per apply CTA
#define NCKB 13          // ceil(25/2) apply CTAs along t

// Scratch (static device globals — allocation-free)
__device__ float g_gp[B_ * TS_ * C_ * C_];   // partial Grams (10.5 MB)
__device__ float g_sxp[B_ * TS_ * C_];       // partial channel sums
__device__ uint16_t g_ath[B_ * 4096];        // gamma*M^T, fp16, swizzled (8KB/batch)

extern __shared__ float smem_dyn[];

__device__ __forceinline__ uint32_t smem_u32(const void* p) {
    uint32_t a;
    asm("{ .reg .u64 t; cvta.to.shared.u64 t, %1; cvt.u32.u64 %0, t; }" : "=r"(a) : "l"(p));
    return a;
}

#define LDSM4(r, addr)                                                       \
    asm volatile("ldmatrix.sync.aligned.m8n8.x4.shared.b16 {%0,%1,%2,%3}, [%4];" \
        : "=r"((r)[0]), "=r"((r)[1]), "=r"((r)[2]), "=r"((r)[3]) : "r"(addr))

#define LDSM4T(r, addr)                                                      \
    asm volatile("ldmatrix.sync.aligned.m8n8.x4.trans.shared.b16 {%0,%1,%2,%3}, [%4];" \
        : "=r"((r)[0]), "=r"((r)[1]), "=r"((r)[2]), "=r"((r)[3]) : "r"(addr))

#define MMAF16(c, a, b0v, b1v)                                               \
    asm volatile("mma.sync.aligned.m16n8k16.row.col.f32.f16.f16.f32 "        \
        "{%0,%1,%2,%3}, {%4,%5,%6,%7}, {%8,%9}, {%0,%1,%2,%3};"              \
        : "+f"((c)[0]), "+f"((c)[1]), "+f"((c)[2]), "+f"((c)[3])             \
        : "r"((a)[0]), "r"((a)[1]), "r"((a)[2]), "r"((a)[3]),                \
          "r"(b0v), "r"(b1v))

#define CP16(dst, src, sz)                                                   \
    asm volatile("cp.async.cg.shared.global [%0], [%1], 16, %2;"             \
        :: "r"(dst), "l"(src), "r"(sz) : "memory")
#define CP_COMMIT()  asm volatile("cp.async.commit_group;" ::: "memory")
#define CP_WAIT(n)   asm volatile("cp.async.wait_group %0;" :: "n"(n) : "memory")

__device__ __forceinline__ uint2 cvt_h4(float4 v) {
    __half2 p0 = __floats2half2_rn(v.x, v.y);
    __half2 p1 = __floats2half2_rn(v.z, v.w);
    uint2 r;
    r.x = *(uint32_t*)&p0;
    r.y = *(uint32_t*)&p1;
    return r;
}

// ---------------------------------------------------------------------------
// Kernel A (HMMA fp16 + cp.async pipeline): partial Gram over a 400-t split.
// Grid (TS_, B_), 256 threads = 8 warps tiling 64x64 as 4m x 2n.
// 3-slot fp32 cp.async ring (2 stage-groups in flight) -> per-thread convert
// (own data only, no sync needed) -> double-buffered fp16 -> 1 sync -> MMA.
// ---------------------------------------------------------------------------
__global__ void __launch_bounds__(256) k_gram_mma(const float* __restrict__ x) {
    char* ring = (char*)smem_dyn;                 // 3 x [64 rows x 272B] = 52224 B
    uint16_t* hbuf = (uint16_t*)(ring + 52224);   // 2 x 8KB fp16 swizzled
    __shared__ float red[256];

    const int split = blockIdx.x, b = blockIdx.y;
    const int tid = threadIdx.x, lane = tid & 31, wid = tid >> 5;
    const int mg = wid >> 1, ng = wid & 1;
    const uint32_t hbase = smem_u32(hbuf);

    const int srow = tid >> 2, sq = tid & 3;
    const float* xsrc = x + ((size_t)b * C_ + srow) * T_ + split * TSPAN + sq * 16;
    const uint32_t rmy = smem_u32(ring) + srow * 272 + sq * 64;
    char* rmyp = ring + srow * 272 + sq * 64;

    // ldmatrix lane addressing (identical to R7)
    const int arow = 16 * mg + (lane & 7) + 8 * ((lane >> 3) & 1);
    const int achk = lane >> 4;
    const int brow0 = 32 * ng + 8 * (lane >> 4) + (lane & 7);
    const int brow1 = brow0 + 16;
    const int bchk = (lane >> 3) & 1;

    float D[4][4];
#pragma unroll
    for (int j = 0; j < 4; ++j)
#pragma unroll
        for (int i = 0; i < 4; ++i) D[j][i] = 0.f;
    float sx = 0.f;

#define G_ISSUE(s) do {                                                      \
    const uint32_t _d = rmy + ((s) % 3) * 17408;                             \
    const int _sz = ((s) < NSTG - 1 || sq == 0) ? 16 : 0;                    \
    const float* _sp = _sz ? (xsrc + (s) * 64) : xsrc;                       \
    CP16(_d,      _sp,      _sz);                                            \
    CP16(_d + 16, _sp + 4,  _sz);                                            \
    CP16(_d + 32, _sp + 8,  _sz);                                            \
    CP16(_d + 48, _sp + 12, _sz);                                            \
    CP_COMMIT();                                                             \
} while (0)

    G_ISSUE(0);
    G_ISSUE(1);

#pragma unroll 1
    for (int s = 0; s < NSTG; ++s) {
        CP_WAIT(1);                               // stage s landed (own groups)
        char* rp = rmyp + (s % 3) * 17408;
        uint16_t* hb = hbuf + (s & 1) * 4096;
#pragma unroll
        for (int i = 0; i < 4; ++i) {
            float4 v = *(const float4*)(rp + 16 * i);
            sx += v.x + v.y + v.z + v.w;
            uint2 hp = cvt_h4(v);
            const int col = sq * 16 + 4 * i;
            const int ad = srow * 128 + ((((col >> 3) ^ (srow & 7))) << 4) + ((col & 7) << 1);
            *(uint2*)((char*)hb + ad) = hp;
        }
        if (s + 2 < NSTG) G_ISSUE(s + 2);
        __syncthreads();

        const uint32_t sbb = hbase + (s & 1) * 8192;
#pragma unroll
        for (int k = 0; k < 4; ++k) {
            const int c0 = k * 2;
            uint32_t a[4], bh[8];
            LDSM4(a, sbb + arow * 128 + (((c0 + achk) ^ (arow & 7)) << 4));
            LDSM4(bh + 0, sbb + brow0 * 128 + (((c0 + bchk) ^ (brow0 & 7)) << 4));
            LDSM4(bh + 4, sbb + brow1 * 128 + (((c0 + bchk) ^ (brow1 & 7)) << 4));
#pragma unroll
            for (int j = 0; j < 4; ++j)
                MMAF16(D[j], a, bh[2 * j], bh[2 * j + 1]);
        }
    }

    // channel sums (4 threads per channel)
    red[tid] = sx;
    __syncthreads();
    if (tid < 64)
        g_sxp[(b * TS_ + split) * C_ + tid] =
            red[4 * tid] + red[4 * tid + 1] + red[4 * tid + 2] + red[4 * tid + 3];

    // write D tile
    float* gp = g_gp + (size_t)(b * TS_ + split) * (C_ * C_);
    const int crow = 16 * mg + (lane >> 2);
    const int ccol0 = 32 * ng + 2 * (lane & 3);
#pragma unroll
    for (int j = 0; j < 4; ++j) {
        const int c = ccol0 + 8 * j;
        *(float2*)(gp + crow * C_ + c)       = make_float2(D[j][0], D[j][1]);
        *(float2*)(gp + (crow + 8) * C_ + c) = make_float2(D[j][2], D[j][3]);
    }
}

// ---------------------------------------------------------------------------
// Kernel B: reduce partials, E~[c][e] = S11*G + S21*sx[e], min-max + softmax,
// then emit gamma*M^T as fp16 in apply's swizzled layout.
// ---------------------------------------------------------------------------
__global__ void __launch_bounds__(256) k_attn(const float* __restrict__ w1,
                                              const float* __restrict__ b1,
                                              const float* __restrict__ w2,
                                              const float* __restrict__ b2,
                                              const float* __restrict__ gptr) {
    __shared__ float Es[C_][65];
    __shared__ float sxs[C_];
    const int b = blockIdx.x;
    const int tid = threadIdx.x;

    float S11 = 0.f, S21 = 0.f;
#pragma unroll
    for (int j = 0; j < 8; ++j) { S11 += w1[j] * w2[j]; S21 += b1[j] * w2[j]; }
    const float ga = *gptr;

    if (tid < 64) {
        float s = 0.f;
#pragma unroll
        for (int p = 0; p < TS_; ++p) s += g_sxp[(b * TS_ + p) * C_ + tid];
        sxs[tid] = s;
    }
    __syncthreads();

    const float* gp = g_gp + (size_t)b * TS_ * (C_ * C_);
    for (int i = tid; i < C_ * C_; i += 256) {
        float g = 0.f;
#pragma unroll
        for (int p = 0; p < TS_; ++p) g += gp[p * (C_ * C_) + i];
        const int e = i & 63;
        Es[i >> 6][e] = S11 * g + S21 * sxs[e];
    }
    __syncthreads();

    const int wid = tid >> 5, lane = tid & 31;
    char* ath = (char*)g_ath + (size_t)b * 8192;
    for (int r = wid; r < C_; r += 8) {
        float v0 = Es[r][lane], v1 = Es[r][lane + 32];
        float mx = fmaxf(v0, v1), mn = fminf(v0, v1);
#pragma unroll
        for (int o = 16; o; o >>= 1) {
            mx = fmaxf(mx, __shfl_xor_sync(0xffffffffu, mx, o));
            mn = fminf(mn, __shfl_xor_sync(0xffffffffu, mn, o));
        }
        const float inv = 1.f / (mx - mn + 1e-8f);
        const float nmax = (mx - mn) * inv;
        float e0 = expf((v0 - mn) * inv - nmax);
        float e1 = expf((v1 - mn) * inv - nmax);
        float s = e0 + e1;
#pragma unroll
        for (int o = 16; o; o >>= 1) s += __shfl_xor_sync(0xffffffffu, s, o);
        const float invs = ga / s;     // fold gamma into M
        const __half h0 = __float2half_rn(e0 * invs);
        const __half h1 = __float2half_rn(e1 * invs);
        // store M[r][c] at apply's swizzled Mt address: c*128 + (((r>>3)^(c&7))<<4) + ((r&7)<<1)
        const int c0 = lane, c1 = lane + 32;
        *(uint16_t*)(ath + c0 * 128 + (((r >> 3) ^ (c0 & 7)) << 4) + ((r & 7) << 1)) =
            *(const uint16_t*)&h0;
        *(uint16_t*)(ath + c1 * 128 + (((r >> 3) ^ (c1 & 7)) << 4) + ((r & 7) << 1)) =
            *(const uint16_t*)&h1;
    }
}

// ---------------------------------------------------------------------------
// Kernel C (HMMA fp16 + cp.async pipeline): out = x + (gamma*M)^T X.
// Grid (NCKB, B_), 256 threads. Each CTA: 2 chunks of 160 t; x for chunk c+1
// streams in via cp.async during chunk c's MMA. M staged once (raw 8KB copy).
// ---------------------------------------------------------------------------
__global__ void __launch_bounds__(256) k_apply_mma(const float* __restrict__ x,
                                                   float* __restrict__ out) {
    uint16_t* At = (uint16_t*)smem_dyn;     // 8 KB fp16 swizzled (gamma*M^T)
    uint16_t* Xs = At + 4096;               // 24 KB fp16 [64][192] swizzled
    float*    Xf = (float*)(Xs + 64 * 192); // 40 KB fp32 linear stage (2560 f4)

    const int b = blockIdx.y, ckb = blockIdx.x;
    const int tid = threadIdx.x, lane = tid & 31, wid = tid >> 5;
    const int mg = wid >> 1, ngw = wid & 1;

    // stage At once: raw vector copy (layout already swizzled + gamma-folded)
    {
        const float4* src = (const float4*)((const char*)g_ath + (size_t)b * 8192);
        float4* dst = (float4*)At;
        dst[tid] = src[tid];
        dst[tid + 256] = src[tid + 256];
    }

    const float* xb = x + (size_t)b * C_ * T_;
    const uint32_t xfb = smem_u32(Xf);

#define A_ISSUE(ck) do {                                                     \
    const int _t0 = (ck) * TC_C;                                             \
    _Pragma("unroll")                                                        \
    for (int k = 0; k < 10; ++k) {                                           \
        const int v = tid + k * 256;                                         \
        const int row = v / 40, q = v % 40;                                  \
        CP16(xfb + v * 16, xb + (size_t)row * T_ + _t0 + 4 * q, 16);         \
    }                                                                        \
    CP_COMMIT();                                                             \
} while (0)

    const int c0 = ckb * CHPC;
    A_ISSUE(c0);

    const uint32_t baseA = smem_u32(At);
    const uint32_t baseX = smem_u32(Xs);
    const int arow = 16 * mg + (lane & 7) + 8 * ((lane >> 3) & 1);
    const int achk = lane >> 4;
    const int bkoff = 8 * ((lane >> 3) & 1) + (lane & 7);
    const int bjj = lane >> 4;
    const int orow = 16 * mg + (lane >> 2);

#pragma unroll 1
    for (int j = 0; j < CHPC; ++j) {
        const int ck = c0 + j;
        if (ck >= NCH_C) break;
        const int t0 = ck * TC_C;

        CP_WAIT(0);                       // chunk ck's fp32 data landed (own)
        // convert own data fp32 -> fp16 swizzled
#pragma unroll
        for (int k = 0; k < 10; ++k) {
            const int v = tid + k * 256;
            const int row = v / 40, q = v % 40;
            float4 w = *(const float4*)(Xf + v * 4);
            uint2 hp = cvt_h4(w);
            const int col = 4 * q;
            const int ad = row * 384 + ((((col >> 3) ^ (row & 7))) << 4) + ((col & 7) << 1);
            *(uint2*)((char*)Xs + ad) = hp;
        }
        // stream next chunk during MMA
        if (j + 1 < CHPC && ck + 1 < NCH_C) A_ISSUE(ck + 1);
        __syncthreads();

        float acc[10][4];
#pragma unroll
        for (int jj = 0; jj < 10; ++jj)
#pragma unroll
            for (int i = 0; i < 4; ++i) acc[jj][i] = 0.f;

#pragma unroll
        for (int kk = 0; kk < 4; ++kk) {
            uint32_t ah[4];
            LDSM4(ah, baseA + arow * 128 + (((kk * 2 + achk) ^ (arow & 7)) << 4));
            const int krow = kk * 16 + bkoff;
#pragma unroll
            for (int p = 0; p < 5; ++p) {
                const int nchunk = ngw * 10 + 2 * p + bjj;
                uint32_t bh[4];
                LDSM4T(bh, baseX + krow * 384 + ((nchunk ^ (krow & 7)) << 4));
                MMAF16(acc[2 * p],     ah, bh[0], bh[1]);
                MMAF16(acc[2 * p + 1], ah, bh[2], bh[3]);
            }
        }

        // epilogue: out = x + acc (gamma already folded into M)
        float* ob = out + (size_t)b * C_ * T_ + t0;
        const float* xg = xb + t0;
#pragma unroll
        for (int jj = 0; jj < 10; ++jj) {
            const int tc = ngw * 80 + 8 * jj + 2 * (lane & 3);
            float2 x0 = *(const float2*)(xg + (size_t)orow * T_ + tc);
            float2 x1 = *(const float2*)(xg + (size_t)(orow + 8) * T_ + tc);
            float2 o0 = make_float2(acc[jj][0] + x0.x, acc[jj][1] + x0.y);
            float2 o1 = make_float2(acc[jj][2] + x1.x, acc[jj][3] + x1.y);
            *(float2*)(ob + (size_t)orow * T_ + tc) = o0;
            *(float2*)(ob + (size_t)(orow + 8) * T_ + tc) = o1;
        }
        __syncthreads();                  // MMA reads done before next convert
    }
}

// ---------------------------------------------------------------------------
extern "C" void kernel_launch(void* const* d_in, const int* in_sizes, int n_in,
                              void* d_out, int out_size) {
    const float* x  = (const float*)d_in[0];
    const float* w1 = (const float*)d_in[1];
    const float* b1 = (const float*)d_in[2];
    const float* w2 = (const float*)d_in[3];
    const float* b2 = (const float*)d_in[4];
    const float* gm = (const float*)d_in[5];
    float* out = (float*)d_out;

    const int smem_gram  = 52224 + 2 * 8192;            // 68,608 B
    const int smem_apply = 8192 + 24576 + 40960;        // 73,728 B
    cudaFuncSetAttribute(k_gram_mma,  cudaFuncAttributeMaxDynamicSharedMemorySize, smem_gram);
    cudaFuncSetAttribute(k_apply_mma, cudaFuncAttributeMaxDynamicSharedMemorySize, smem_apply);

    k_gram_mma<<<dim3(TS_, B_), 256, smem_gram>>>(x);
    k_attn<<<B_, 256>>>(w1, b1, w2, b2, gm);
    k_apply_mma<<<dim3(NCKB, B_), 256, smem_apply>>>(x, out);
}